// round 1
// baseline (speedup 1.0000x reference)
#include <cuda_runtime.h>

// Problem constants
#define MROWS 100000
#define FDIM  256
#define DDIM  128
#define NHOP  3
#define NE    1600000

// Scratch: per-hop feature projection fw = X @ W_feat[hop]  -> [MROWS][128]
__device__ float g_fw[(size_t)MROWS * DDIM];
// Folded weight matrix [256][512]: cols 0..383 = W_feat[0..2], cols 384..511 = alpha * W_embed @ (sum_h W_embK[h])
__device__ float g_Wcomb[FDIM * 4 * DDIM];

// ---------------------------------------------------------------------------
// Fold kernel: build g_Wcomb. grid=256 (k), block=512 (j)
// ---------------------------------------------------------------------------
__global__ void fold_kernel(const float* __restrict__ W_embed,   // [256][128]
                            const float* __restrict__ W_feat,    // [3][256][128]
                            const float* __restrict__ W_embK,    // [3][128][128]
                            const float* __restrict__ alpha_p)
{
    int k = blockIdx.x;      // 0..255
    int j = threadIdx.x;     // 0..511
    float r;
    if (j < 3 * DDIM) {
        int hop = j >> 7;
        int jj  = j & 127;
        r = W_feat[((size_t)hop * FDIM + k) * DDIM + jj];
    } else {
        int jj = j - 3 * DDIM;
        float s = 0.f;
        #pragma unroll 4
        for (int d = 0; d < DDIM; d++) {
            float wc = W_embK[d * DDIM + jj]
                     + W_embK[DDIM * DDIM + d * DDIM + jj]
                     + W_embK[2 * DDIM * DDIM + d * DDIM + jj];
            s += W_embed[k * DDIM + d] * wc;
        }
        r = alpha_p[0] * s;
    }
    g_Wcomb[k * (4 * DDIM) + j] = r;
}

// ---------------------------------------------------------------------------
// SGEMM: C[jb block] = X[100000,256] @ Wcomb[:, jb*128 : (jb+1)*128]
// 128x128 tile per block, BK=32, 256 threads, 8x8 per thread.
// jb==3 writes the alpha*learned baseline directly into d_out;
// jb<3 writes into g_fw.
// ---------------------------------------------------------------------------
__global__ void __launch_bounds__(256, 2)
gemm_kernel(const float* __restrict__ X, float* __restrict__ outp, int jb)
{
    __shared__ float As[32][128];   // transposed X tile: As[k][m]
    __shared__ float Bs[32][128];   // Bs[k][n]

    float* Cdst = (jb == 3) ? outp : g_fw;

    int row0 = blockIdx.x * 128;
    int tid  = threadIdx.x;
    int tr   = tid >> 4;            // 0..15
    int tc   = tid & 15;            // 0..15

    float acc[8][8];
    #pragma unroll
    for (int i = 0; i < 8; i++)
        #pragma unroll
        for (int j = 0; j < 8; j++)
            acc[i][j] = 0.f;

    const float* Bbase = g_Wcomb + jb * DDIM;

    for (int k0 = 0; k0 < FDIM; k0 += 32) {
        // Load X tile 128x32, store transposed
        #pragma unroll
        for (int i = 0; i < 4; i++) {
            int idx = tid + 256 * i;     // 0..1023 float4 slots
            int r   = idx >> 3;          // 0..127 row
            int c4  = idx & 7;           // float4 within row
            float4 v = make_float4(0.f, 0.f, 0.f, 0.f);
            int gr = row0 + r;
            if (gr < MROWS)
                v = *(const float4*)(X + (size_t)gr * FDIM + k0 + c4 * 4);
            As[c4 * 4 + 0][r] = v.x;
            As[c4 * 4 + 1][r] = v.y;
            As[c4 * 4 + 2][r] = v.z;
            As[c4 * 4 + 3][r] = v.w;
        }
        // Load B tile 32x128
        #pragma unroll
        for (int i = 0; i < 4; i++) {
            int idx = tid + 256 * i;
            int kr  = idx >> 5;          // 0..31
            int c4  = idx & 31;          // float4 within row
            *(float4*)(&Bs[kr][c4 * 4]) =
                *(const float4*)(Bbase + (size_t)(k0 + kr) * (4 * DDIM) + c4 * 4);
        }
        __syncthreads();

        #pragma unroll 8
        for (int kk = 0; kk < 32; kk++) {
            float a[8], b[8];
            *(float4*)(a)     = *(float4*)(&As[kk][tr * 8]);
            *(float4*)(a + 4) = *(float4*)(&As[kk][tr * 8 + 4]);
            *(float4*)(b)     = *(float4*)(&Bs[kk][tc * 8]);
            *(float4*)(b + 4) = *(float4*)(&Bs[kk][tc * 8 + 4]);
            #pragma unroll
            for (int i = 0; i < 8; i++)
                #pragma unroll
                for (int j = 0; j < 8; j++)
                    acc[i][j] += a[i] * b[j];
        }
        __syncthreads();
    }

    #pragma unroll
    for (int i = 0; i < 8; i++) {
        int gr = row0 + tr * 8 + i;
        if (gr < MROWS) {
            float* dst = Cdst + (size_t)gr * DDIM + tc * 8;
            *(float4*)(dst)     = *(float4*)(&acc[i][0]);
            *(float4*)(dst + 4) = *(float4*)(&acc[i][4]);
        }
    }
}

// ---------------------------------------------------------------------------
// SpMM scatter: one warp per edge, lane covers 4 of the 128 output floats.
// out[row] += val * g_fw[col]  via red.global.add.v4.f32
// ---------------------------------------------------------------------------
__global__ void spmm_kernel(const int*   __restrict__ rows,
                            const int*   __restrict__ cols,
                            const float* __restrict__ vals,
                            float*       __restrict__ outp)
{
    int warp = (int)((blockIdx.x * (size_t)blockDim.x + threadIdx.x) >> 5);
    int lane = threadIdx.x & 31;
    if (warp >= NE) return;

    int   r = rows[warp];
    int   c = cols[warp];
    float v = vals[warp];

    const float4 f = *(const float4*)(g_fw + (size_t)c * DDIM + lane * 4);
    float* dst = outp + (size_t)r * DDIM + lane * 4;
    asm volatile("red.global.add.v4.f32 [%0], {%1, %2, %3, %4};"
                 :: "l"(dst), "f"(f.x * v), "f"(f.y * v), "f"(f.z * v), "f"(f.w * v)
                 : "memory");
}

// ---------------------------------------------------------------------------
// ReLU epilogue
// ---------------------------------------------------------------------------
__global__ void relu_kernel(float* __restrict__ outp)
{
    size_t i = (size_t)blockIdx.x * blockDim.x + threadIdx.x;
    const size_t total4 = (size_t)MROWS * DDIM / 4;
    if (i < total4) {
        float4* p = (float4*)outp;
        float4 v = p[i];
        v.x = fmaxf(v.x, 0.f);
        v.y = fmaxf(v.y, 0.f);
        v.z = fmaxf(v.z, 0.f);
        v.w = fmaxf(v.w, 0.f);
        p[i] = v;
    }
}

// ---------------------------------------------------------------------------
extern "C" void kernel_launch(void* const* d_in, const int* in_sizes, int n_in,
                              void* d_out, int out_size)
{
    const float* X       = (const float*)d_in[0];   // [100000][256]
    const int*   erow    = (const int*)  d_in[1];   // [3][1600000]
    const int*   ecol    = (const int*)  d_in[2];   // [3][1600000]
    const float* eval    = (const float*)d_in[3];   // [3][1600000]
    const float* W_embed = (const float*)d_in[4];   // [256][128]
    const float* W_feat  = (const float*)d_in[5];   // [3][256][128]
    const float* W_embK  = (const float*)d_in[6];   // [3][128][128]
    const float* alpha   = (const float*)d_in[7];   // [1]
    float* outp = (float*)d_out;                    // [100000][128]

    (void)in_sizes; (void)n_in; (void)out_size;

    // 1. Fold weights: Wcomb = [W_feat0 | W_feat1 | W_feat2 | alpha*W_embed@(sum W_embK)]
    fold_kernel<<<256, 512>>>(W_embed, W_feat, W_embK, alpha);

    const int gemm_grid = (MROWS + 127) / 128;   // 782

    // 2. Baseline: out = alpha * X @ (W_embed @ sum_h W_embK[h])
    gemm_kernel<<<gemm_grid, 256>>>(X, outp, 3);

    // 3. Per hop: fw = X @ W_feat[hop], then scatter-add A_hop @ fw into out
    for (int hop = 0; hop < NHOP; hop++) {
        gemm_kernel<<<gemm_grid, 256>>>(X, outp, hop);
        const int spmm_blocks = (NE * 32 + 255) / 256;   // 200000
        spmm_kernel<<<spmm_blocks, 256>>>(erow + (size_t)hop * NE,
                                          ecol + (size_t)hop * NE,
                                          eval + (size_t)hop * NE,
                                          outp);
    }

    // 4. ReLU
    const size_t total4 = (size_t)MROWS * DDIM / 4;
    relu_kernel<<<(int)((total4 + 255) / 256), 256>>>(outp);
}

// round 5
// speedup vs baseline: 1.4573x; 1.4573x over previous
#include <cuda_runtime.h>
#include <cuda_bf16.h>
#include <mma.h>
#include <cstdint>

using namespace nvcuda;

// Problem constants
#define MROWS 100000
#define FDIM  256
#define DDIM  128
#define NHOP  3
#define NE    1600000
#define NCOLS 512              // 3*128 fw blocks + 128 baseline block
#define MB    782              // ceil(100000/128)

// ---------------------------------------------------------------------------
// Device scratch
// ---------------------------------------------------------------------------
__device__ float          g_fw[(size_t)NHOP * MROWS * DDIM];   // per-hop fw
__device__ __nv_bfloat16  g_Wth[(size_t)NCOLS * FDIM];         // Wcomb^T hi [512][256]
__device__ __nv_bfloat16  g_Wtl[(size_t)NCOLS * FDIM];         // Wcomb^T lo [512][256]

__device__ __forceinline__ uint32_t pack_bf2(__nv_bfloat16 lo, __nv_bfloat16 hi) {
    __nv_bfloat162 t(lo, hi);
    return *(uint32_t*)&t;
}

// ---------------------------------------------------------------------------
// Fold kernel: build Wcomb^T in bf16 hi/lo.  grid=256 (k), block=512 (j)
// j<384: W_feat[j/128][k][j%128]; j>=384: alpha*(W_embed @ sum_h W_embK[h])[k][j-384]
// ---------------------------------------------------------------------------
__global__ void fold_kernel(const float* __restrict__ W_embed,
                            const float* __restrict__ W_feat,
                            const float* __restrict__ W_embK,
                            const float* __restrict__ alpha_p)
{
    int k = blockIdx.x;
    int j = threadIdx.x;
    float r;
    if (j < 3 * DDIM) {
        int hop = j >> 7;
        int jj  = j & 127;
        r = W_feat[((size_t)hop * FDIM + k) * DDIM + jj];
    } else {
        int jj = j - 3 * DDIM;
        float s = 0.f;
        #pragma unroll 4
        for (int d = 0; d < DDIM; d++) {
            float wc = W_embK[d * DDIM + jj]
                     + W_embK[DDIM * DDIM + d * DDIM + jj]
                     + W_embK[2 * DDIM * DDIM + d * DDIM + jj];
            s += W_embed[k * DDIM + d] * wc;
        }
        r = alpha_p[0] * s;
    }
    __nv_bfloat16 h = __float2bfloat16(r);
    g_Wth[(size_t)j * FDIM + k] = h;
    g_Wtl[(size_t)j * FDIM + k] = __float2bfloat16(r - __bfloat162float(h));
}

// ---------------------------------------------------------------------------
// wmma GEMM: C = X @ Wcomb, bf16 hi/lo 3-split, fp32 accum.
// grid = (4 N-blocks, 782 M-blocks), 256 threads, 128x128 CTA tile, BK=32.
// Warp w: warp_m = (w&1)*64, warp_n = (w>>1)*32 -> 64x32 warp tile,
// acc = 4x2 wmma 16x16x16 fragments.
// Smem rows: 48 halves (96 B) -> 32-byte-aligned fragment pointers, ldm mult of 8.
// ---------------------------------------------------------------------------
#define ROWH   48                       // halves per smem row (32 used + 16 pad)
#define TILE_H (128 * ROWH)             // halves per tile

__global__ void __launch_bounds__(256, 2)
mm_kernel(const float* __restrict__ X, float* __restrict__ outp)
{
    __shared__ __align__(32) __nv_bfloat16 smem[4 * TILE_H];   // 49152 bytes
    __nv_bfloat16* sAh = smem;
    __nv_bfloat16* sAl = smem + TILE_H;
    __nv_bfloat16* sBh = smem + 2 * TILE_H;
    __nv_bfloat16* sBl = smem + 3 * TILE_H;

    int tid  = threadIdx.x;
    int wid  = tid >> 5;
    int lane = tid & 31;
    int nb   = blockIdx.x;            // 0..3
    int mb   = blockIdx.y;            // 0..781
    int row0 = mb * 128;
    int n0   = nb * 128;
    int warp_m = (wid & 1) * 64;
    int warp_n = (wid >> 1) * 32;

    wmma::fragment<wmma::accumulator, 16, 16, 16, float> acc[4][2];
    #pragma unroll
    for (int i = 0; i < 4; i++)
        #pragma unroll
        for (int j = 0; j < 2; j++)
            wmma::fill_fragment(acc[i][j], 0.f);

    for (int k0 = 0; k0 < FDIM; k0 += 32) {
        // ---- load A (fp32 -> bf16 hi/lo inline) : 128 rows x 32 halves ----
        #pragma unroll
        for (int t = 0; t < 4; t++) {
            int idx = tid + 256 * t;     // 0..1023
            int row = idx >> 3;          // 0..127
            int c4  = idx & 7;           // 4-float chunk
            float4 v = make_float4(0.f, 0.f, 0.f, 0.f);
            int gr = row0 + row;
            if (gr < MROWS)
                v = *(const float4*)(X + (size_t)gr * FDIM + k0 + c4 * 4);
            __nv_bfloat16 h0 = __float2bfloat16(v.x);
            __nv_bfloat16 h1 = __float2bfloat16(v.y);
            __nv_bfloat16 h2 = __float2bfloat16(v.z);
            __nv_bfloat16 h3 = __float2bfloat16(v.w);
            uint2 hi = make_uint2(pack_bf2(h0, h1), pack_bf2(h2, h3));
            uint2 lo = make_uint2(
                pack_bf2(__float2bfloat16(v.x - __bfloat162float(h0)),
                         __float2bfloat16(v.y - __bfloat162float(h1))),
                pack_bf2(__float2bfloat16(v.z - __bfloat162float(h2)),
                         __float2bfloat16(v.w - __bfloat162float(h3))));
            *(uint2*)(sAh + row * ROWH + c4 * 4) = hi;
            *(uint2*)(sAl + row * ROWH + c4 * 4) = lo;
        }
        // ---- load B hi/lo (already bf16): 128 n-rows x 32 k-halves ----
        #pragma unroll
        for (int t = 0; t < 2; t++) {
            int idx = tid + 256 * t;     // 0..511
            int row = idx >> 2;          // 0..127
            int ch  = idx & 3;           // 8-half chunk
            size_t goff = (size_t)(n0 + row) * FDIM + k0 + ch * 8;
            *(uint4*)(sBh + row * ROWH + ch * 8) = *(const uint4*)(g_Wth + goff);
            *(uint4*)(sBl + row * ROWH + ch * 8) = *(const uint4*)(g_Wtl + goff);
        }
        __syncthreads();

        #pragma unroll
        for (int s = 0; s < 2; s++) {
            wmma::fragment<wmma::matrix_b, 16, 16, 16, __nv_bfloat16, wmma::col_major> bh[2], bl[2];
            #pragma unroll
            for (int j = 0; j < 2; j++) {
                const __nv_bfloat16* bp = sBh + (warp_n + j * 16) * ROWH + s * 16;
                const __nv_bfloat16* lp = sBl + (warp_n + j * 16) * ROWH + s * 16;
                wmma::load_matrix_sync(bh[j], bp, ROWH);
                wmma::load_matrix_sync(bl[j], lp, ROWH);
            }
            #pragma unroll
            for (int i = 0; i < 4; i++) {
                wmma::fragment<wmma::matrix_a, 16, 16, 16, __nv_bfloat16, wmma::row_major> ah, al;
                wmma::load_matrix_sync(ah, sAh + (warp_m + i * 16) * ROWH + s * 16, ROWH);
                wmma::load_matrix_sync(al, sAl + (warp_m + i * 16) * ROWH + s * 16, ROWH);
                #pragma unroll
                for (int j = 0; j < 2; j++) {
                    wmma::mma_sync(acc[i][j], ah, bh[j], acc[i][j]);
                    wmma::mma_sync(acc[i][j], ah, bl[j], acc[i][j]);
                    wmma::mma_sync(acc[i][j], al, bh[j], acc[i][j]);
                }
            }
        }
        __syncthreads();
    }

    // ---- epilogue ----
    float* base = (nb == 3) ? outp : (g_fw + (size_t)nb * MROWS * DDIM);
    if (row0 + 128 <= MROWS) {
        #pragma unroll
        for (int i = 0; i < 4; i++)
            #pragma unroll
            for (int j = 0; j < 2; j++)
                wmma::store_matrix_sync(base + (size_t)(row0 + warp_m + i * 16) * DDIM
                                             + warp_n + j * 16,
                                        acc[i][j], DDIM, wmma::mem_row_major);
    } else {
        // Boundary CTA: stage each fragment through smem, guarded scalar copy.
        float* warp_st = (float*)smem + wid * 256;    // smem reuse safe after final barrier
        #pragma unroll
        for (int i = 0; i < 4; i++)
            #pragma unroll
            for (int j = 0; j < 2; j++) {
                wmma::store_matrix_sync(warp_st, acc[i][j], 16, wmma::mem_row_major);
                __syncwarp();
                int r  = lane >> 1;          // 0..15
                int cc = (lane & 1) * 8;
                int gr = row0 + warp_m + i * 16 + r;
                if (gr < MROWS) {
                    #pragma unroll
                    for (int q = 0; q < 8; q++)
                        base[(size_t)gr * DDIM + warp_n + j * 16 + cc + q] = warp_st[r * 16 + cc + q];
                }
                __syncwarp();
            }
    }
}

// ---------------------------------------------------------------------------
// SpMM scatter: one warp per edge, lane covers 4 of the 128 output floats.
// NOTE: fw pointer computed IN DEVICE CODE from the __device__ symbol —
// passing (g_fw + off) from host passes the host shadow address (ATS-readable
// zeros on GB300), which was the silent R3/R4 bug.
// ---------------------------------------------------------------------------
__global__ void spmm_kernel(const int*   __restrict__ rows,
                            const int*   __restrict__ cols,
                            const float* __restrict__ vals,
                            int hop,
                            float* __restrict__ outp)
{
    const float* fwp = g_fw + (size_t)hop * MROWS * DDIM;

    int warp = (int)((blockIdx.x * (size_t)blockDim.x + threadIdx.x) >> 5);
    int lane = threadIdx.x & 31;
    if (warp >= NE) return;

    int   r = rows[warp];
    int   c = cols[warp];
    float v = vals[warp];

    const float4 f = *(const float4*)(fwp + (size_t)c * DDIM + lane * 4);
    float* dst = outp + (size_t)r * DDIM + lane * 4;
    asm volatile("red.global.add.v4.f32 [%0], {%1, %2, %3, %4};"
                 :: "l"(dst), "f"(f.x * v), "f"(f.y * v), "f"(f.z * v), "f"(f.w * v)
                 : "memory");
}

// ---------------------------------------------------------------------------
// ReLU epilogue
// ---------------------------------------------------------------------------
__global__ void relu_kernel(float* __restrict__ outp)
{
    size_t i = (size_t)blockIdx.x * blockDim.x + threadIdx.x;
    const size_t total4 = (size_t)MROWS * DDIM / 4;
    if (i < total4) {
        float4* p = (float4*)outp;
        float4 v = p[i];
        v.x = fmaxf(v.x, 0.f);
        v.y = fmaxf(v.y, 0.f);
        v.z = fmaxf(v.z, 0.f);
        v.w = fmaxf(v.w, 0.f);
        p[i] = v;
    }
}

// ---------------------------------------------------------------------------
extern "C" void kernel_launch(void* const* d_in, const int* in_sizes, int n_in,
                              void* d_out, int out_size)
{
    const float* X       = (const float*)d_in[0];
    const int*   erow    = (const int*)  d_in[1];
    const int*   ecol    = (const int*)  d_in[2];
    const float* eval    = (const float*)d_in[3];
    const float* W_embed = (const float*)d_in[4];
    const float* W_feat  = (const float*)d_in[5];
    const float* W_embK  = (const float*)d_in[6];
    const float* alpha   = (const float*)d_in[7];
    float* outp = (float*)d_out;

    (void)in_sizes; (void)n_in; (void)out_size;

    // 1. Fold weights -> Wcomb^T bf16 hi/lo
    fold_kernel<<<256, 512>>>(W_embed, W_feat, W_embK, alpha);

    // 2. One wmma GEMM for all 4 column blocks (fw x3 + baseline -> d_out)
    mm_kernel<<<dim3(4, MB), 256>>>(X, outp);

    // 3. Per hop scatter-add (hop index passed; pointer derived in device code)
    for (int hop = 0; hop < NHOP; hop++) {
        const int spmm_blocks = (NE * 32 + 255) / 256;
        spmm_kernel<<<spmm_blocks, 256>>>(erow + (size_t)hop * NE,
                                          ecol + (size_t)hop * NE,
                                          eval + (size_t)hop * NE,
                                          hop,
                                          outp);
    }

    // 4. ReLU
    const size_t total4 = (size_t)MROWS * DDIM / 4;
    relu_kernel<<<(int)((total4 + 255) / 256), 256>>>(outp);
}

// round 6
// speedup vs baseline: 1.7700x; 1.2146x over previous
#include <cuda_runtime.h>
#include <cuda_bf16.h>
#include <mma.h>
#include <cstdint>

using namespace nvcuda;

// Problem constants
#define MROWS 100000
#define FDIM  256
#define DDIM  128
#define NHOP  3
#define NE    1600000
#define NCOLS 512              // 3*128 fw blocks + 128 baseline block
#define MB    782              // ceil(100000/128)
#define SCANB 98               // ceil(100000/1024)

// ---------------------------------------------------------------------------
// Device scratch
// ---------------------------------------------------------------------------
__device__ float          g_fw[(size_t)NHOP * MROWS * DDIM];   // per-hop fw
__device__ __nv_bfloat16  g_Wth[(size_t)NCOLS * FDIM];         // Wcomb^T hi [512][256]
__device__ __nv_bfloat16  g_Wtl[(size_t)NCOLS * FDIM];         // Wcomb^T lo [512][256]
__device__ int            g_rowptr[NHOP * MROWS];              // per-hop exclusive prefix
__device__ int            g_cur[NHOP * MROWS];                 // histogram, then cursor
__device__ int            g_aux[NHOP * 128];                   // scan block sums
__device__ int2           g_ecv[(size_t)NHOP * NE];            // CSR-ordered {col, val}

__device__ __forceinline__ uint32_t pack_bf2(__nv_bfloat16 lo, __nv_bfloat16 hi) {
    __nv_bfloat162 t(lo, hi);
    return *(uint32_t*)&t;
}

// ---------------------------------------------------------------------------
// Fold kernel: build Wcomb^T in bf16 hi/lo.  grid=256 (k), block=512 (j)
// ---------------------------------------------------------------------------
__global__ void fold_kernel(const float* __restrict__ W_embed,
                            const float* __restrict__ W_feat,
                            const float* __restrict__ W_embK,
                            const float* __restrict__ alpha_p)
{
    int k = blockIdx.x;
    int j = threadIdx.x;
    float r;
    if (j < 3 * DDIM) {
        int hop = j >> 7;
        int jj  = j & 127;
        r = W_feat[((size_t)hop * FDIM + k) * DDIM + jj];
    } else {
        int jj = j - 3 * DDIM;
        float s = 0.f;
        #pragma unroll 4
        for (int d = 0; d < DDIM; d++) {
            float wc = W_embK[d * DDIM + jj]
                     + W_embK[DDIM * DDIM + d * DDIM + jj]
                     + W_embK[2 * DDIM * DDIM + d * DDIM + jj];
            s += W_embed[k * DDIM + d] * wc;
        }
        r = alpha_p[0] * s;
    }
    __nv_bfloat16 h = __float2bfloat16(r);
    g_Wth[(size_t)j * FDIM + k] = h;
    g_Wtl[(size_t)j * FDIM + k] = __float2bfloat16(r - __bfloat162float(h));
}

// ---------------------------------------------------------------------------
// wmma GEMM (unchanged from passing R5 kernel)
// ---------------------------------------------------------------------------
#define ROWH   48
#define TILE_H (128 * ROWH)

__global__ void __launch_bounds__(256, 2)
mm_kernel(const float* __restrict__ X, float* __restrict__ outp)
{
    __shared__ __align__(32) __nv_bfloat16 smem[4 * TILE_H];
    __nv_bfloat16* sAh = smem;
    __nv_bfloat16* sAl = smem + TILE_H;
    __nv_bfloat16* sBh = smem + 2 * TILE_H;
    __nv_bfloat16* sBl = smem + 3 * TILE_H;

    int tid  = threadIdx.x;
    int wid  = tid >> 5;
    int lane = tid & 31;
    int nb   = blockIdx.x;
    int mb   = blockIdx.y;
    int row0 = mb * 128;
    int n0   = nb * 128;
    int warp_m = (wid & 1) * 64;
    int warp_n = (wid >> 1) * 32;

    wmma::fragment<wmma::accumulator, 16, 16, 16, float> acc[4][2];
    #pragma unroll
    for (int i = 0; i < 4; i++)
        #pragma unroll
        for (int j = 0; j < 2; j++)
            wmma::fill_fragment(acc[i][j], 0.f);

    for (int k0 = 0; k0 < FDIM; k0 += 32) {
        #pragma unroll
        for (int t = 0; t < 4; t++) {
            int idx = tid + 256 * t;
            int row = idx >> 3;
            int c4  = idx & 7;
            float4 v = make_float4(0.f, 0.f, 0.f, 0.f);
            int gr = row0 + row;
            if (gr < MROWS)
                v = *(const float4*)(X + (size_t)gr * FDIM + k0 + c4 * 4);
            __nv_bfloat16 h0 = __float2bfloat16(v.x);
            __nv_bfloat16 h1 = __float2bfloat16(v.y);
            __nv_bfloat16 h2 = __float2bfloat16(v.z);
            __nv_bfloat16 h3 = __float2bfloat16(v.w);
            uint2 hi = make_uint2(pack_bf2(h0, h1), pack_bf2(h2, h3));
            uint2 lo = make_uint2(
                pack_bf2(__float2bfloat16(v.x - __bfloat162float(h0)),
                         __float2bfloat16(v.y - __bfloat162float(h1))),
                pack_bf2(__float2bfloat16(v.z - __bfloat162float(h2)),
                         __float2bfloat16(v.w - __bfloat162float(h3))));
            *(uint2*)(sAh + row * ROWH + c4 * 4) = hi;
            *(uint2*)(sAl + row * ROWH + c4 * 4) = lo;
        }
        #pragma unroll
        for (int t = 0; t < 2; t++) {
            int idx = tid + 256 * t;
            int row = idx >> 2;
            int ch  = idx & 3;
            size_t goff = (size_t)(n0 + row) * FDIM + k0 + ch * 8;
            *(uint4*)(sBh + row * ROWH + ch * 8) = *(const uint4*)(g_Wth + goff);
            *(uint4*)(sBl + row * ROWH + ch * 8) = *(const uint4*)(g_Wtl + goff);
        }
        __syncthreads();

        #pragma unroll
        for (int s = 0; s < 2; s++) {
            wmma::fragment<wmma::matrix_b, 16, 16, 16, __nv_bfloat16, wmma::col_major> bh[2], bl[2];
            #pragma unroll
            for (int j = 0; j < 2; j++) {
                wmma::load_matrix_sync(bh[j], sBh + (warp_n + j * 16) * ROWH + s * 16, ROWH);
                wmma::load_matrix_sync(bl[j], sBl + (warp_n + j * 16) * ROWH + s * 16, ROWH);
            }
            #pragma unroll
            for (int i = 0; i < 4; i++) {
                wmma::fragment<wmma::matrix_a, 16, 16, 16, __nv_bfloat16, wmma::row_major> ah, al;
                wmma::load_matrix_sync(ah, sAh + (warp_m + i * 16) * ROWH + s * 16, ROWH);
                wmma::load_matrix_sync(al, sAl + (warp_m + i * 16) * ROWH + s * 16, ROWH);
                #pragma unroll
                for (int j = 0; j < 2; j++) {
                    wmma::mma_sync(acc[i][j], ah, bh[j], acc[i][j]);
                    wmma::mma_sync(acc[i][j], ah, bl[j], acc[i][j]);
                    wmma::mma_sync(acc[i][j], al, bh[j], acc[i][j]);
                }
            }
        }
        __syncthreads();
    }

    float* base = (nb == 3) ? outp : (g_fw + (size_t)nb * MROWS * DDIM);
    if (row0 + 128 <= MROWS) {
        #pragma unroll
        for (int i = 0; i < 4; i++)
            #pragma unroll
            for (int j = 0; j < 2; j++)
                wmma::store_matrix_sync(base + (size_t)(row0 + warp_m + i * 16) * DDIM
                                             + warp_n + j * 16,
                                        acc[i][j], DDIM, wmma::mem_row_major);
    } else {
        float* warp_st = (float*)smem + wid * 256;
        #pragma unroll
        for (int i = 0; i < 4; i++)
            #pragma unroll
            for (int j = 0; j < 2; j++) {
                wmma::store_matrix_sync(warp_st, acc[i][j], 16, wmma::mem_row_major);
                __syncwarp();
                int r  = lane >> 1;
                int cc = (lane & 1) * 8;
                int gr = row0 + warp_m + i * 16 + r;
                if (gr < MROWS) {
                    #pragma unroll
                    for (int q = 0; q < 8; q++)
                        base[(size_t)gr * DDIM + warp_n + j * 16 + cc + q] = warp_st[r * 16 + cc + q];
                }
                __syncwarp();
            }
    }
}

// ---------------------------------------------------------------------------
// CSR build: zero -> histogram -> scan(3 kernels) -> scatter {col,val}
// ---------------------------------------------------------------------------
__global__ void zero_kernel()
{
    int i = blockIdx.x * blockDim.x + threadIdx.x;
    if (i < NHOP * MROWS) g_cur[i] = 0;
}

__global__ void hist_kernel(const int* __restrict__ erow)
{
    int idx = blockIdx.x * blockDim.x + threadIdx.x;   // 0 .. 3*NE-1
    if (idx >= NHOP * NE) return;
    int hop = idx / NE;
    int r   = erow[idx];
    atomicAdd(&g_cur[hop * MROWS + r], 1);
}

// Block-level exclusive scan over g_cur -> g_rowptr, block sums -> g_aux.
__global__ void scan1_kernel()
{
    int hop = blockIdx.y;
    int i   = blockIdx.x * 1024 + threadIdx.x;
    int tid = threadIdx.x;
    int lane = tid & 31, wid = tid >> 5;

    int v = (i < MROWS) ? g_cur[hop * MROWS + i] : 0;
    int s = v;
    #pragma unroll
    for (int d = 1; d < 32; d <<= 1) {
        int t = __shfl_up_sync(0xffffffffu, s, d);
        if (lane >= d) s += t;
    }
    __shared__ int wsum[32];
    if (lane == 31) wsum[wid] = s;
    __syncthreads();
    if (wid == 0) {
        int ws = wsum[lane];
        #pragma unroll
        for (int d = 1; d < 32; d <<= 1) {
            int t = __shfl_up_sync(0xffffffffu, ws, d);
            if (lane >= d) ws += t;
        }
        wsum[lane] = ws;
    }
    __syncthreads();
    int base = (wid > 0) ? wsum[wid - 1] : 0;
    int incl = base + s;
    if (i < MROWS) g_rowptr[hop * MROWS + i] = incl - v;   // exclusive within block
    if (tid == 1023) g_aux[hop * 128 + blockIdx.x] = incl;
}

__global__ void scan2_kernel()
{
    int t = threadIdx.x;
    if (t < NHOP) {
        int s = 0;
        for (int k = 0; k < SCANB; k++) {
            int v = g_aux[t * 128 + k];
            g_aux[t * 128 + k] = s;
            s += v;
        }
    }
}

__global__ void scan3_kernel()
{
    int hop = blockIdx.y;
    int i   = blockIdx.x * 1024 + threadIdx.x;
    if (i < MROWS) {
        int v = g_rowptr[hop * MROWS + i] + g_aux[hop * 128 + blockIdx.x];
        g_rowptr[hop * MROWS + i] = v;
        g_cur[hop * MROWS + i]    = v;     // cursor for scatter
    }
}

__global__ void scatter_kernel(const int* __restrict__ erow,
                               const int* __restrict__ ecol,
                               const float* __restrict__ eval)
{
    int idx = blockIdx.x * blockDim.x + threadIdx.x;
    if (idx >= NHOP * NE) return;
    int hop = idx / NE;
    int r   = erow[idx];
    int pos = atomicAdd(&g_cur[hop * MROWS + r], 1);
    g_ecv[(size_t)hop * NE + pos] = make_int2(ecol[idx], __float_as_int(eval[idx]));
}

// ---------------------------------------------------------------------------
// Gather SpMM + relu fused: one warp per output row, all 3 hops, no atomics.
// Lane handles 4 of 128 floats. 2-stage software pipeline on the fw gathers.
// ---------------------------------------------------------------------------
__global__ void __launch_bounds__(256)
gather_kernel(float* __restrict__ outp)
{
    int gw   = (int)((blockIdx.x * (size_t)blockDim.x + threadIdx.x) >> 5);
    int lane = threadIdx.x & 31;
    if (gw >= MROWS) return;

    float4 acc = make_float4(0.f, 0.f, 0.f, 0.f);

    #pragma unroll
    for (int hop = 0; hop < NHOP; hop++) {
        int start = g_rowptr[hop * MROWS + gw];
        int end   = (gw == MROWS - 1) ? NE : g_rowptr[hop * MROWS + gw + 1];
        const int2*  ecv = g_ecv + (size_t)hop * NE;
        const float* fw  = g_fw  + (size_t)hop * MROWS * DDIM;

        for (int b = start; b < end; b += 32) {
            int n = end - b;
            if (n > 32) n = 32;
            int c = 0; float v = 0.f;
            if (lane < n) {
                int2 t = ecv[b + lane];
                c = t.x;
                v = __int_as_float(t.y);
            }
            // 2-stage pipelined reduction over the n edges
            int c0 = __shfl_sync(0xffffffffu, c, 0);
            float4 f = *(const float4*)(fw + (size_t)c0 * DDIM + lane * 4);
            for (int j = 0; j < n; j++) {
                float4 fn;
                if (j + 1 < n) {
                    int cn = __shfl_sync(0xffffffffu, c, j + 1);
                    fn = *(const float4*)(fw + (size_t)cn * DDIM + lane * 4);
                }
                float vv = __shfl_sync(0xffffffffu, v, j);
                acc.x += vv * f.x;
                acc.y += vv * f.y;
                acc.z += vv * f.z;
                acc.w += vv * f.w;
                f = fn;
            }
        }
    }

    float* dst = outp + (size_t)gw * DDIM + lane * 4;
    float4 o = *(float4*)dst;
    o.x = fmaxf(o.x + acc.x, 0.f);
    o.y = fmaxf(o.y + acc.y, 0.f);
    o.z = fmaxf(o.z + acc.z, 0.f);
    o.w = fmaxf(o.w + acc.w, 0.f);
    *(float4*)dst = o;
}

// ---------------------------------------------------------------------------
extern "C" void kernel_launch(void* const* d_in, const int* in_sizes, int n_in,
                              void* d_out, int out_size)
{
    const float* X       = (const float*)d_in[0];
    const int*   erow    = (const int*)  d_in[1];
    const int*   ecol    = (const int*)  d_in[2];
    const float* eval    = (const float*)d_in[3];
    const float* W_embed = (const float*)d_in[4];
    const float* W_feat  = (const float*)d_in[5];
    const float* W_embK  = (const float*)d_in[6];
    const float* alpha   = (const float*)d_in[7];
    float* outp = (float*)d_out;

    (void)in_sizes; (void)n_in; (void)out_size;

    // --- CSR build (independent of GEMM; all on the one stream) ---
    zero_kernel<<<(NHOP * MROWS + 255) / 256, 256>>>();
    hist_kernel<<<(NHOP * NE + 255) / 256, 256>>>(erow);
    scan1_kernel<<<dim3(SCANB, NHOP), 1024>>>();
    scan2_kernel<<<1, 32>>>();
    scan3_kernel<<<dim3(SCANB, NHOP), 1024>>>();
    scatter_kernel<<<(NHOP * NE + 255) / 256, 256>>>(erow, ecol, eval);

    // --- dense path ---
    fold_kernel<<<256, 512>>>(W_embed, W_feat, W_embK, alpha);
    mm_kernel<<<dim3(4, MB), 256>>>(X, outp);

    // --- gather SpMM (all hops) + relu, atomic-free ---
    gather_kernel<<<(MROWS * 32 + 255) / 256, 256>>>(outp);
}